// round 13
// baseline (speedup 1.0000x reference)
#include <cuda_runtime.h>
#include <cstdint>

#define BATCH  32
#define HW     3136
#define C      256
#define CR     64
#define PPC    16            // pixels per chunk
#define CHUNKS 196           // HW / PPC
#define NG     32            // channel groups of 8 floats (C/8)

// Scratch (allocation-free per harness rules)
__device__ float g_partial[BATCH * CHUNKS * C];
__device__ float g_gate[BATCH * C];

// 256-bit load, pin line in L2 (evict_last) — R9's fastest gap load
__device__ __forceinline__ void ld256_evict_last(const float* p, uint32_t* u) {
    asm volatile("ld.global.nc.L2::evict_last.v8.b32 {%0,%1,%2,%3,%4,%5,%6,%7}, [%8];"
                 : "=r"(u[0]), "=r"(u[1]), "=r"(u[2]), "=r"(u[3]),
                   "=r"(u[4]), "=r"(u[5]), "=r"(u[6]), "=r"(u[7])
                 : "l"(p));
}
// 256-bit plain load
__device__ __forceinline__ void ld256(const float* p, uint32_t* u) {
    asm volatile("ld.global.nc.v8.b32 {%0,%1,%2,%3,%4,%5,%6,%7}, [%8];"
                 : "=r"(u[0]), "=r"(u[1]), "=r"(u[2]), "=r"(u[3]),
                   "=r"(u[4]), "=r"(u[5]), "=r"(u[6]), "=r"(u[7])
                 : "l"(p));
}
// 256-bit plain store
__device__ __forceinline__ void st256(float* p, const uint32_t* u) {
    asm volatile("st.global.v8.b32 [%0], {%1,%2,%3,%4,%5,%6,%7,%8};"
                 :: "l"(p),
                    "r"(u[0]), "r"(u[1]), "r"(u[2]), "r"(u[3]),
                    "r"(u[4]), "r"(u[5]), "r"(u[6]), "r"(u[7]));
}

// ---------------------------------------------------------------------------
// gap_kernel: R9's exact fastest configuration (18.9us, 5.68 TB/s).
// grid = (CHUNKS, BATCH) = 6272 blocks, 256 threads. evict_last v8 loads;
// PLAIN partial store (keeps partials L2-resident for fc's latency chain).
// ---------------------------------------------------------------------------
__global__ __launch_bounds__(256) void gap_kernel(const float* __restrict__ x)
{
    const int chunk = blockIdx.x;
    const int b     = blockIdx.y;
    const int tid   = threadIdx.x;
    const int c8    = tid & (NG - 1);
    const int pr    = tid >> 5;

    const float* xp = x + ((size_t)(b * HW + chunk * PPC + pr)) * C + c8 * 8;

    uint32_t u0[8], u1[8];
    ld256_evict_last(xp,                 u0);
    ld256_evict_last(xp + (size_t)8 * C, u1);

    __shared__ float red[8 * C];       // 8KB
    float* rp = &red[pr * C + c8 * 8];
#pragma unroll
    for (int k = 0; k < 8; ++k) {
        rp[k] = __uint_as_float(u0[k]) + __uint_as_float(u1[k]);
    }
    __syncthreads();

    float p0 = 0.0f;
#pragma unroll
    for (int g = 0; g < 8; ++g) {
        p0 += red[g * C + tid];
    }
    g_partial[(b * CHUNKS + chunk) * C + tid] = p0;   // plain: stays in L2
}

// ---------------------------------------------------------------------------
// fc_kernel: 32 blocks x 256 threads. 16 independent accumulator chains cut
// the dependent-latency rounds from 49 to ~13; partials are L2-hot (plain
// stores in gap) so each round is ~L2 latency, not DRAM.
// ---------------------------------------------------------------------------
__global__ __launch_bounds__(256) void fc_kernel(const float* __restrict__ w1,
                                                 const float* __restrict__ w2)
{
    const int b = blockIdx.x;
    const int t = threadIdx.x;

    __shared__ float s[C];
    __shared__ float h[CR];

    float a[16];
#pragma unroll
    for (int i = 0; i < 16; ++i) a[i] = 0.0f;

    const float* pp = &g_partial[(size_t)b * CHUNKS * C + t];
    int k = 0;
#pragma unroll 1
    for (; k + 16 <= CHUNKS; k += 16) {
#pragma unroll
        for (int i = 0; i < 16; ++i) {
            a[i] += __ldg(&pp[(size_t)(k + i) * C]);
        }
    }
#pragma unroll
    for (int i = 0; i < 4; ++i) {       // remaining 4 (196 = 12*16 + 4)
        a[i] += __ldg(&pp[(size_t)(k + i) * C]);
    }
#pragma unroll
    for (int i = 8; i > 0; i >>= 1) {
#pragma unroll
        for (int j = 0; j < i; ++j) a[j] += a[j + i];
    }
    s[t] = a[0] * (1.0f / (float)HW);
    __syncthreads();

    if (t < CR) {
        float acc = 0.0f;
#pragma unroll 8
        for (int c = 0; c < C; ++c) {
            acc += s[c] * w1[c * CR + t];
        }
        h[t] = fminf(fmaxf(acc, 0.0f), 6.0f);
    }
    __syncthreads();

    float acc = 0.0f;
#pragma unroll
    for (int r = 0; r < CR; ++r) {
        acc += h[r] * w2[r * C + t];
    }
    g_gate[b * C + t] = fminf(fmaxf(acc + 3.0f, 0.0f), 6.0f) * (1.0f / 6.0f);
}

// ---------------------------------------------------------------------------
// mul_kernel: R11's configuration (best measured mul ~41-43us once fc is
// correctly attributed): grid = (CHUNKS, BATCH) = 6272 blocks, 256 threads,
// plain v8 loads + plain v8 stores, gate in registers.
// ---------------------------------------------------------------------------
__global__ __launch_bounds__(256) void mul_kernel(const float* __restrict__ x,
                                                  float* __restrict__ out)
{
    const int chunk = blockIdx.x;
    const int b     = blockIdx.y;
    const int tid   = threadIdx.x;
    const int c8    = tid & (NG - 1);
    const int pr    = tid >> 5;

    float g[8];
    {
        const float4 ga = __ldg(&((const float4*)g_gate)[b * (C / 4) + c8 * 2]);
        const float4 gb = __ldg(&((const float4*)g_gate)[b * (C / 4) + c8 * 2 + 1]);
        g[0] = ga.x; g[1] = ga.y; g[2] = ga.z; g[3] = ga.w;
        g[4] = gb.x; g[5] = gb.y; g[6] = gb.z; g[7] = gb.w;
    }

    const size_t off = ((size_t)(b * HW + chunk * PPC + pr)) * C + c8 * 8;
    const float* xp = x + off;
    float*       op = out + off;

    uint32_t u0[8], u1[8];
    ld256(xp,                 u0);
    ld256(xp + (size_t)8 * C, u1);

#pragma unroll
    for (int k = 0; k < 8; ++k) {
        u0[k] = __float_as_uint(__uint_as_float(u0[k]) * g[k]);
        u1[k] = __float_as_uint(__uint_as_float(u1[k]) * g[k]);
    }

    st256(op,                 u0);
    st256(op + (size_t)8 * C, u1);
}

extern "C" void kernel_launch(void* const* d_in, const int* in_sizes, int n_in,
                              void* d_out, int out_size) {
    const float* x  = (const float*)d_in[0];
    const float* w1 = (const float*)d_in[1];
    const float* w2 = (const float*)d_in[2];
    float* out      = (float*)d_out;

    dim3 grid(CHUNKS, BATCH);
    gap_kernel<<<grid, 256>>>(x);
    fc_kernel<<<BATCH, 256>>>(w1, w2);
    mul_kernel<<<grid, 256>>>(x, out);
}